// round 14
// baseline (speedup 1.0000x reference)
#include <cuda_runtime.h>

// Problem constants
#define NB     8
#define CIN    2
#define HIN    128
#define WIN    128
#define TT     32
#define CHO    32
#define HP     64
#define WPX    64
#define WPT    4             // wp columns per block (small tile -> 5 blocks/SM)
#define NTHR   256           // 8 warps: warp = 4 ch x 4 wp, lane = t
#define TILE_W 9             // 2*WPT + 1 halo

// smem layout (floats)
#define TILE_F  (CIN * 3 * TILE_W * TT)      // 1728 : input tile [6][9][32]
#define ZBLK    132                           // per-(cg,wp) z block: [t(32)][ch(4)]+pad
#define Z_OFF   TILE_F
#define Z_F     (8 * WPT * ZBLK)              // 4224
#define SW_OFF  (Z_OFF + Z_F)                 // weights [18][32]
#define SW_F    (18 * CHO)                    // 576
#define SB_OFF  (SW_OFF + SW_F)               // spike bitmasks [128]
#define SMEM_BYTES ((SB_OFF + 128) * 4)       // 26624 B ; x5 blocks = 133 KB fits

// packed f32x2 fma: d = a*b + d
__device__ __forceinline__ void fma2(unsigned long long &d,
                                     unsigned long long a,
                                     unsigned long long b) {
    asm("fma.rn.f32x2 %0, %1, %2, %3;" : "=l"(d) : "l"(a), "l"(b), "l"(d));
}
// pack two floats into an f32x2 register pair {lo, hi}
__device__ __forceinline__ unsigned long long pk2(float lo, float hi) {
    unsigned long long r;
    asm("mov.b64 %0, {%1, %2};" : "=l"(r)
        : "r"(__float_as_uint(lo)), "r"(__float_as_uint(hi)));
    return r;
}
__device__ __forceinline__ float f2lo(unsigned long long v) {
    return __uint_as_float((unsigned)(v & 0xffffffffull));
}
__device__ __forceinline__ float f2hi(unsigned long long v) {
    return __uint_as_float((unsigned)(v >> 32));
}

__global__ __launch_bounds__(NTHR, 5)
void snn_encoder_kernel(const float* __restrict__ spike,
                        const float* __restrict__ weight_v,
                        const float* __restrict__ weight_g,
                        const float* __restrict__ delay,
                        float* __restrict__ out) {
    extern __shared__ __align__(16) float smem[];
    float* sin_ = smem;              // [plane(6)][w(9)][t(32)]
    float* zbuf = smem + Z_OFF;      // [(cg*4+wp)][132] = [t*4 + c]
    float* sw   = smem + SW_OFF;     // [tap(18)][ch(32)]
    unsigned int* sb = (unsigned int*)(smem + SB_OFF);   // sbits[128]

    const int tid  = threadIdx.x;
    const int lane = tid & 31;       // phase 1: lane = t
    const int cg   = tid >> 5;       // warp 0..7: channels 4*cg .. 4*cg+3
    const int wp0  = blockIdx.x * WPT;
    const int hp   = blockIdx.y;
    const int n    = blockIdx.z;

    // ---- cooperative input tile load via cp.async (LDGSTS) ----
    const int h0 = 2 * hp - 1;
    const int w0 = 2 * wp0 - 1;
    #pragma unroll
    for (int it = 0; it < 2; it++) {
        const int idx = tid + it * NTHR;
        if (idx < CIN * 3 * TILE_W * 8) {
            const int plane = idx / (TILE_W * 8);        // c*3 + r
            const int rem   = idx - plane * (TILE_W * 8);
            const int wj    = rem >> 3;
            const int t4    = rem & 7;
            const int c = plane / 3;
            const int r = plane - c * 3;
            const int h = h0 + r;
            const int w = w0 + wj;
            const bool ok = ((unsigned)h < HIN) && ((unsigned)w < WIN);
            const float* src = spike +
                (((size_t)(n * CIN + c) * HIN + (ok ? h : 0)) * WIN + (ok ? w : 0)) * TT
                + t4 * 4;
            const unsigned int dst = (unsigned int)__cvta_generic_to_shared(
                sin_ + (plane * TILE_W + wj) * TT + t4 * 4);
            const int sz = ok ? 16 : 0;
            asm volatile("cp.async.cg.shared.global [%0], [%1], 16, %2;"
                         :: "r"(dst), "l"(src), "r"(sz));
        }
    }
    asm volatile("cp.async.commit_group;");

    // ---- weight norm (one thread per output channel), overlaps cp.async ----
    if (tid < 32) {
        float wv[18];
        float ss = 0.f;
        #pragma unroll
        for (int k = 0; k < 18; k++) {
            wv[k] = weight_v[tid * 18 + k];
            ss += wv[k] * wv[k];
        }
        const float sc = weight_g[tid] / sqrtf(ss);
        #pragma unroll
        for (int k = 0; k < 18; k++)
            sw[k * 32 + tid] = wv[k] * sc;
    }

    asm volatile("cp.async.wait_group 0;");
    __syncthreads();

    // ---- PHASE 1: conv. warp = 4 ch x 4 wp, lane = t.
    // Two 9-tap passes over input channel c (36 weight regs each). kw-rolling
    // tap reuse. z channel-interleaved: one STS.128 per (j, pass); pass 2 does
    // LDS.128 + STS.128. Summation order k=0..17 unchanged -> z bit-identical.
    #pragma unroll 1
    for (int cpass = 0; cpass < CIN; cpass++) {
        unsigned long long w01[9], w23[9];
        #pragma unroll
        for (int k = 0; k < 9; k++) {
            const float4 wv = *(const float4*)(sw + (9 * cpass + k) * 32 + 4 * cg);
            w01[k] = pk2(wv.x, wv.y);
            w23[k] = pk2(wv.z, wv.w);
        }
        const float* pl0 = sin_ + (3 * cpass + 0) * TILE_W * TT + lane;
        const float* pl1 = sin_ + (3 * cpass + 1) * TILE_W * TT + lane;
        const float* pl2 = sin_ + (3 * cpass + 2) * TILE_W * TT + lane;
        // rolling kw=0 taps (dup'd) for r = 0,1,2
        float s0 = pl0[0];
        float s1 = pl1[0];
        float s2 = pl2[0];
        unsigned long long tr0 = pk2(s0, s0);
        unsigned long long tr1 = pk2(s1, s1);
        unsigned long long tr2 = pk2(s2, s2);
        #pragma unroll
        for (int j = 0; j < WPT; j++) {
            const int col = 2 * j;
            float* zr = zbuf + (cg * WPT + j) * ZBLK + 4 * lane;
            unsigned long long a01, a23;
            if (cpass == 0) { a01 = 0ull; a23 = 0ull; }
            else {
                const float4 zp = *(const float4*)zr;
                a01 = pk2(zp.x, zp.y);
                a23 = pk2(zp.z, zp.w);
            }
            // r = 0
            {
                const float tb = pl0[(col + 1) * TT];
                const float tc = pl0[(col + 2) * TT];
                const unsigned long long t1 = pk2(tb, tb);
                const unsigned long long t2 = pk2(tc, tc);
                fma2(a01, tr0, w01[0]);  fma2(a23, tr0, w23[0]);
                fma2(a01, t1,  w01[1]);  fma2(a23, t1,  w23[1]);
                fma2(a01, t2,  w01[2]);  fma2(a23, t2,  w23[2]);
                tr0 = t2;
            }
            // r = 1
            {
                const float tb = pl1[(col + 1) * TT];
                const float tc = pl1[(col + 2) * TT];
                const unsigned long long t1 = pk2(tb, tb);
                const unsigned long long t2 = pk2(tc, tc);
                fma2(a01, tr1, w01[3]);  fma2(a23, tr1, w23[3]);
                fma2(a01, t1,  w01[4]);  fma2(a23, t1,  w23[4]);
                fma2(a01, t2,  w01[5]);  fma2(a23, t2,  w23[5]);
                tr1 = t2;
            }
            // r = 2
            {
                const float tb = pl2[(col + 1) * TT];
                const float tc = pl2[(col + 2) * TT];
                const unsigned long long t1 = pk2(tb, tb);
                const unsigned long long t2 = pk2(tc, tc);
                fma2(a01, tr2, w01[6]);  fma2(a23, tr2, w23[6]);
                fma2(a01, t1,  w01[7]);  fma2(a23, t1,  w23[7]);
                fma2(a01, t2,  w01[8]);  fma2(a23, t2,  w23[8]);
                tr2 = t2;
            }
            float4 zo;
            zo.x = f2lo(a01);  zo.y = f2hi(a01);
            zo.z = f2lo(a23);  zo.w = f2hi(a23);
            *(float4*)zr = zo;
        }
    }
    __syncwarp();   // z blocks below are warp-private

    // ---- PHASE 2: LIF scan. 16 active lanes -> warp's 16 (ch,wp) rows ----
    // banks = 4*wp + csub + 4t (mod 32): distinct across active lanes.
    if (lane < 16) {
        const int csub = lane >> 2;            // channel within group (0..3)
        const int wp   = lane & 3;             // wp within tile (0..3)
        const float* zr = zbuf + (cg * WPT + wp) * ZBLK + csub;
        float cur = 0.f, volt = 0.f;
        unsigned int bits = 0u;
        #pragma unroll
        for (int t = 0; t < TT; t++) {
            cur  = cur * 0.75f + zr[4 * t];
            volt = volt * 0.9f + cur;
            const bool s = volt >= 1.0f;
            bits |= s ? (1u << t) : 0u;
            volt  = s ? 0.f : volt;
        }
        sb[(4 * cg + csub) * WPT + wp] = bits;
    }
    __syncthreads();

    // ---- PHASE 3: coalesced epilogue. warp cg writes ch cg + 8*sp ----
    #pragma unroll
    for (int sp = 0; sp < 4; sp++) {
        const int ch = cg + 8 * sp;
        const float d  = delay[ch];           // warp-uniform
        const int   di = (int)floorf(d);
        const float f  = d - (float)di;
        const float onef = 1.0f - f;
        float* obase = out +
            (((size_t)((n * CHO + ch) * HP + hp) * WPX + wp0) * TT);
        {
            const int idx = lane;             // 0..31 float4 slots (4wp x 8)
            const int wpi = idx >> 3;
            const int t   = (idx & 7) * 4;
            const unsigned int bt = sb[ch * WPT + wpi];
            unsigned int b0 = 0u, b1 = 0u;
            if (di >= 0 && di < 32)         b0 = bt << di;
            if (di + 1 >= 0 && di + 1 < 32) b1 = bt << (di + 1);
            float4 v;
            v.x = (((b0 >> (t + 0)) & 1u) ? onef : 0.f) + (((b1 >> (t + 0)) & 1u) ? f : 0.f);
            v.y = (((b0 >> (t + 1)) & 1u) ? onef : 0.f) + (((b1 >> (t + 1)) & 1u) ? f : 0.f);
            v.z = (((b0 >> (t + 2)) & 1u) ? onef : 0.f) + (((b1 >> (t + 2)) & 1u) ? f : 0.f);
            v.w = (((b0 >> (t + 3)) & 1u) ? onef : 0.f) + (((b1 >> (t + 3)) & 1u) ? f : 0.f);
            *(float4*)(obase + idx * 4) = v;
        }
    }
}

extern "C" void kernel_launch(void* const* d_in, const int* in_sizes, int n_in,
                              void* d_out, int out_size) {
    const float* spike    = (const float*)d_in[0];
    const float* weight_v = (const float*)d_in[1];
    const float* weight_g = (const float*)d_in[2];
    const float* delay    = (const float*)d_in[3];
    float* out = (float*)d_out;

    cudaFuncSetAttribute(snn_encoder_kernel,
                         cudaFuncAttributeMaxDynamicSharedMemorySize, SMEM_BYTES);
    dim3 grid(WPX / WPT, HP, NB);   // (16, 64, 8) = 8192 blocks
    snn_encoder_kernel<<<grid, NTHR, SMEM_BYTES>>>(spike, weight_v, weight_g, delay, out);
}

// round 15
// speedup vs baseline: 1.3420x; 1.3420x over previous
#include <cuda_runtime.h>

// Problem constants
#define NB     8
#define CIN    2
#define HIN    128
#define WIN    128
#define TT     32
#define CHO    32
#define HP     64
#define WPX    64
#define WPT    8             // wp columns per block
#define NTHR   256           // 8 warps: warp = 4 ch x 8 wp, lane = t
#define TILE_W 17            // 2*WPT + 1 halo

// smem layout (floats)
#define TILE_F  (CIN * 3 * TILE_W * TT)      // 3264 : input tile [6][17][32]
#define ZBLK    132                           // per-(cg,wp) z block: [t(32)][ch(4)]+pad
#define Z_OFF   TILE_F
#define Z_F     (8 * WPT * ZBLK)              // 8448
#define SW_OFF  (Z_OFF + Z_F)                 // weights [18][32]
#define SW_F    (18 * CHO)                    // 576
#define SB_OFF  (SW_OFF + SW_F)               // spike bitmasks [256]
#define SMEM_BYTES ((SB_OFF + 256) * 4)       // 50176 B ; x4 blocks = 200704 fits

// packed f32x2 fma: d = a*b + d
__device__ __forceinline__ void fma2(unsigned long long &d,
                                     unsigned long long a,
                                     unsigned long long b) {
    asm("fma.rn.f32x2 %0, %1, %2, %3;" : "=l"(d) : "l"(a), "l"(b), "l"(d));
}
// pack two floats into an f32x2 register pair {lo, hi}
__device__ __forceinline__ unsigned long long pk2(float lo, float hi) {
    unsigned long long r;
    asm("mov.b64 %0, {%1, %2};" : "=l"(r)
        : "r"(__float_as_uint(lo)), "r"(__float_as_uint(hi)));
    return r;
}
__device__ __forceinline__ float f2lo(unsigned long long v) {
    return __uint_as_float((unsigned)(v & 0xffffffffull));
}
__device__ __forceinline__ float f2hi(unsigned long long v) {
    return __uint_as_float((unsigned)(v >> 32));
}

__global__ __launch_bounds__(NTHR, 4)
void snn_encoder_kernel(const float* __restrict__ spike,
                        const float* __restrict__ weight_v,
                        const float* __restrict__ weight_g,
                        const float* __restrict__ delay,
                        float* __restrict__ out) {
    extern __shared__ __align__(16) float smem[];
    float* sin_ = smem;              // [plane(6)][w(17)][t(32)]
    float* zbuf = smem + Z_OFF;      // [(cg*8+wp)][132] = [t*4 + c]
    float* sw   = smem + SW_OFF;     // [tap(18)][ch(32)]
    unsigned int* sb = (unsigned int*)(smem + SB_OFF);   // sbits[256]

    const int tid  = threadIdx.x;
    const int lane = tid & 31;       // phase 1: lane = t
    const int cg   = tid >> 5;       // warp 0..7: channels 4*cg .. 4*cg+3
    const int wp0  = blockIdx.x * WPT;
    const int hp   = blockIdx.y;
    const int n    = blockIdx.z;

    // ---- cooperative input tile load via cp.async (LDGSTS) ----
    const int h0 = 2 * hp - 1;
    const int w0 = 2 * wp0 - 1;
    #pragma unroll
    for (int it = 0; it < 4; it++) {
        const int idx = tid + it * NTHR;
        if (idx < CIN * 3 * TILE_W * 8) {
            const int plane = idx / (TILE_W * 8);        // c*3 + r
            const int rem   = idx - plane * (TILE_W * 8);
            const int wj    = rem >> 3;
            const int t4    = rem & 7;
            const int c = plane / 3;
            const int r = plane - c * 3;
            const int h = h0 + r;
            const int w = w0 + wj;
            const bool ok = ((unsigned)h < HIN) && ((unsigned)w < WIN);
            const float* src = spike +
                (((size_t)(n * CIN + c) * HIN + (ok ? h : 0)) * WIN + (ok ? w : 0)) * TT
                + t4 * 4;
            const unsigned int dst = (unsigned int)__cvta_generic_to_shared(
                sin_ + (plane * TILE_W + wj) * TT + t4 * 4);
            const int sz = ok ? 16 : 0;
            asm volatile("cp.async.cg.shared.global [%0], [%1], 16, %2;"
                         :: "r"(dst), "l"(src), "r"(sz));
        }
    }
    asm volatile("cp.async.commit_group;");

    // ---- weight norm (one thread per output channel), overlaps cp.async ----
    if (tid < 32) {
        float wv[18];
        float ss = 0.f;
        #pragma unroll
        for (int k = 0; k < 18; k++) {
            wv[k] = weight_v[tid * 18 + k];
            ss += wv[k] * wv[k];
        }
        const float sc = weight_g[tid] / sqrtf(ss);
        #pragma unroll
        for (int k = 0; k < 18; k++)
            sw[k * 32 + tid] = wv[k] * sc;
    }

    asm volatile("cp.async.wait_group 0;");
    __syncthreads();

    // ---- PHASE 1: conv. warp = 4 ch x 8 wp, lane = t.
    // j-groups of 4 with register-resident accumulators: pass c=0 fills 4
    // accumulator pairs, weights swap (smem broadcast reload), pass c=1
    // accumulates onto the same registers, z stored ONCE per j (no pass-2
    // LDS/STS roundtrip). FMA order per output still k=0..17 sequential ->
    // z bit-identical to round 13.
    #pragma unroll 1
    for (int jg = 0; jg < 2; jg++) {
        const int colb = 8 * jg;                  // column base of this j-group
        unsigned long long acc01[4], acc23[4];

        // ---- pass c = 0 ----
        {
            unsigned long long w01[9], w23[9];
            #pragma unroll
            for (int k = 0; k < 9; k++) {
                const float4 wv = *(const float4*)(sw + k * 32 + 4 * cg);
                w01[k] = pk2(wv.x, wv.y);
                w23[k] = pk2(wv.z, wv.w);
            }
            const float* pl0 = sin_ + 0 * TILE_W * TT + lane;
            const float* pl1 = sin_ + 1 * TILE_W * TT + lane;
            const float* pl2 = sin_ + 2 * TILE_W * TT + lane;
            float s0 = pl0[colb * TT];
            float s1 = pl1[colb * TT];
            float s2 = pl2[colb * TT];
            unsigned long long tr0 = pk2(s0, s0);
            unsigned long long tr1 = pk2(s1, s1);
            unsigned long long tr2 = pk2(s2, s2);
            #pragma unroll
            for (int j2 = 0; j2 < 4; j2++) {
                const int col = colb + 2 * j2;
                unsigned long long a01 = 0ull, a23 = 0ull;
                {
                    const float tb = pl0[(col + 1) * TT];
                    const float tc = pl0[(col + 2) * TT];
                    const unsigned long long t1 = pk2(tb, tb);
                    const unsigned long long t2 = pk2(tc, tc);
                    fma2(a01, tr0, w01[0]);  fma2(a23, tr0, w23[0]);
                    fma2(a01, t1,  w01[1]);  fma2(a23, t1,  w23[1]);
                    fma2(a01, t2,  w01[2]);  fma2(a23, t2,  w23[2]);
                    tr0 = t2;
                }
                {
                    const float tb = pl1[(col + 1) * TT];
                    const float tc = pl1[(col + 2) * TT];
                    const unsigned long long t1 = pk2(tb, tb);
                    const unsigned long long t2 = pk2(tc, tc);
                    fma2(a01, tr1, w01[3]);  fma2(a23, tr1, w23[3]);
                    fma2(a01, t1,  w01[4]);  fma2(a23, t1,  w23[4]);
                    fma2(a01, t2,  w01[5]);  fma2(a23, t2,  w23[5]);
                    tr1 = t2;
                }
                {
                    const float tb = pl2[(col + 1) * TT];
                    const float tc = pl2[(col + 2) * TT];
                    const unsigned long long t1 = pk2(tb, tb);
                    const unsigned long long t2 = pk2(tc, tc);
                    fma2(a01, tr2, w01[6]);  fma2(a23, tr2, w23[6]);
                    fma2(a01, t1,  w01[7]);  fma2(a23, t1,  w23[7]);
                    fma2(a01, t2,  w01[8]);  fma2(a23, t2,  w23[8]);
                    tr2 = t2;
                }
                acc01[j2] = a01;
                acc23[j2] = a23;
            }
        }

        // ---- pass c = 1 (weights swapped; accumulate on registers, store z) ----
        {
            unsigned long long w01[9], w23[9];
            #pragma unroll
            for (int k = 0; k < 9; k++) {
                const float4 wv = *(const float4*)(sw + (9 + k) * 32 + 4 * cg);
                w01[k] = pk2(wv.x, wv.y);
                w23[k] = pk2(wv.z, wv.w);
            }
            const float* pl0 = sin_ + 3 * TILE_W * TT + lane;
            const float* pl1 = sin_ + 4 * TILE_W * TT + lane;
            const float* pl2 = sin_ + 5 * TILE_W * TT + lane;
            float s0 = pl0[colb * TT];
            float s1 = pl1[colb * TT];
            float s2 = pl2[colb * TT];
            unsigned long long tr0 = pk2(s0, s0);
            unsigned long long tr1 = pk2(s1, s1);
            unsigned long long tr2 = pk2(s2, s2);
            #pragma unroll
            for (int j2 = 0; j2 < 4; j2++) {
                const int col = colb + 2 * j2;
                unsigned long long a01 = acc01[j2], a23 = acc23[j2];
                {
                    const float tb = pl0[(col + 1) * TT];
                    const float tc = pl0[(col + 2) * TT];
                    const unsigned long long t1 = pk2(tb, tb);
                    const unsigned long long t2 = pk2(tc, tc);
                    fma2(a01, tr0, w01[0]);  fma2(a23, tr0, w23[0]);
                    fma2(a01, t1,  w01[1]);  fma2(a23, t1,  w23[1]);
                    fma2(a01, t2,  w01[2]);  fma2(a23, t2,  w23[2]);
                    tr0 = t2;
                }
                {
                    const float tb = pl1[(col + 1) * TT];
                    const float tc = pl1[(col + 2) * TT];
                    const unsigned long long t1 = pk2(tb, tb);
                    const unsigned long long t2 = pk2(tc, tc);
                    fma2(a01, tr1, w01[3]);  fma2(a23, tr1, w23[3]);
                    fma2(a01, t1,  w01[4]);  fma2(a23, t1,  w23[4]);
                    fma2(a01, t2,  w01[5]);  fma2(a23, t2,  w23[5]);
                    tr1 = t2;
                }
                {
                    const float tb = pl2[(col + 1) * TT];
                    const float tc = pl2[(col + 2) * TT];
                    const unsigned long long t1 = pk2(tb, tb);
                    const unsigned long long t2 = pk2(tc, tc);
                    fma2(a01, tr2, w01[6]);  fma2(a23, tr2, w23[6]);
                    fma2(a01, t1,  w01[7]);  fma2(a23, t1,  w23[7]);
                    fma2(a01, t2,  w01[8]);  fma2(a23, t2,  w23[8]);
                    tr2 = t2;
                }
                float* zr = zbuf + (cg * WPT + (4 * jg + j2)) * ZBLK + 4 * lane;
                float4 zo;
                zo.x = f2lo(a01);  zo.y = f2hi(a01);
                zo.z = f2lo(a23);  zo.w = f2hi(a23);
                *(float4*)zr = zo;
            }
        }
    }
    __syncwarp();   // z blocks below are warp-private

    // ---- PHASE 2: LIF scan. lane -> one of this warp's 32 (ch,wp) rows ----
    // banks = 4*(lane&7) + (lane>>3) + 4t (mod 32): conflict-free.
    {
        const int csub = lane >> 3;            // channel within group
        const int wp   = lane & 7;
        const float* zr = zbuf + (cg * WPT + wp) * ZBLK + csub;
        float cur = 0.f, volt = 0.f;
        unsigned int bits = 0u;
        #pragma unroll
        for (int t = 0; t < TT; t++) {
            cur  = cur * 0.75f + zr[4 * t];
            volt = volt * 0.9f + cur;
            const bool s = volt >= 1.0f;
            bits |= s ? (1u << t) : 0u;
            volt  = s ? 0.f : volt;
        }
        sb[(4 * cg + csub) * WPT + wp] = bits;
    }
    __syncthreads();

    // ---- PHASE 3: coalesced epilogue. warp cg writes ch cg + 8*sp ----
    #pragma unroll
    for (int sp = 0; sp < 4; sp++) {
        const int ch = cg + 8 * sp;
        const float d  = delay[ch];           // warp-uniform
        const int   di = (int)floorf(d);
        const float f  = d - (float)di;
        const float onef = 1.0f - f;
        float* obase = out +
            (((size_t)((n * CHO + ch) * HP + hp) * WPX + wp0) * TT);
        #pragma unroll
        for (int i = 0; i < 2; i++) {
            const int idx = i * 32 + lane;    // 0..63 float4 slots (8wp x 8)
            const int wpi = idx >> 3;
            const int t   = (idx & 7) * 4;
            const unsigned int bt = sb[ch * WPT + wpi];
            unsigned int b0 = 0u, b1 = 0u;
            if (di >= 0 && di < 32)         b0 = bt << di;
            if (di + 1 >= 0 && di + 1 < 32) b1 = bt << (di + 1);
            float4 v;
            v.x = (((b0 >> (t + 0)) & 1u) ? onef : 0.f) + (((b1 >> (t + 0)) & 1u) ? f : 0.f);
            v.y = (((b0 >> (t + 1)) & 1u) ? onef : 0.f) + (((b1 >> (t + 1)) & 1u) ? f : 0.f);
            v.z = (((b0 >> (t + 2)) & 1u) ? onef : 0.f) + (((b1 >> (t + 2)) & 1u) ? f : 0.f);
            v.w = (((b0 >> (t + 3)) & 1u) ? onef : 0.f) + (((b1 >> (t + 3)) & 1u) ? f : 0.f);
            *(float4*)(obase + idx * 4) = v;
        }
    }
}

extern "C" void kernel_launch(void* const* d_in, const int* in_sizes, int n_in,
                              void* d_out, int out_size) {
    const float* spike    = (const float*)d_in[0];
    const float* weight_v = (const float*)d_in[1];
    const float* weight_g = (const float*)d_in[2];
    const float* delay    = (const float*)d_in[3];
    float* out = (float*)d_out;

    cudaFuncSetAttribute(snn_encoder_kernel,
                         cudaFuncAttributeMaxDynamicSharedMemorySize, SMEM_BYTES);
    dim3 grid(WPX / WPT, HP, NB);   // (8, 64, 8) = 4096 blocks
    snn_encoder_kernel<<<grid, NTHR, SMEM_BYTES>>>(spike, weight_v, weight_g, delay, out);
}